// round 13
// baseline (speedup 1.0000x reference)
#include <cuda_runtime.h>
#include <cuda_bf16.h>
#include <cstdint>

#define S       512
#define TMAXX   2048
#define OBS     1024
#define CL      4
#define BPC     4
#define NT      512
#define NCTAS   128

// chunk = [4 b][16 n] bf16 (128B) + zp float4 (16B) + pad (16B)
#define CHUNKB  160
#define SLICE2  1280          // 8 chunks
#define BUF2    5120          // 4 slices

// smem layout (bytes)
#define B_OFF   0             // [2][BUF2] = 10240
#define CP_OFF  10240         // cp[8 pair][2 kh][16 n][4 b] f32 = 4096
#define TS_OFF  (CP_OFF + 4096 + 128)   // pad for benign B-fragment overreads
#define BAR_OFF (TS_OFF + 16) // barF[2][4] = 64B
#define SMEM_BYTES (BAR_OFF + 64)

// ---------------- device tables ----------------
__device__ float g_expA[S * S];      // [n][p]
__device__ float g_expEt[OBS * S];   // [o][n]
__device__ float g_expPi[S];

// ---------------- helpers ----------------
__device__ __forceinline__ float warp_max(float v) {
    #pragma unroll
    for (int o = 16; o; o >>= 1) v = fmaxf(v, __shfl_xor_sync(0xffffffffu, v, o));
    return v;
}
__device__ __forceinline__ float warp_sum(float v) {
    #pragma unroll
    for (int o = 16; o; o >>= 1) v += __shfl_xor_sync(0xffffffffu, v, o);
    return v;
}
__device__ __forceinline__ uint32_t mapa_u32(uint32_t addr, int rank) {
    uint32_t r;
    asm("mapa.shared::cluster.u32 %0, %1, %2;" : "=r"(r) : "r"(addr), "r"(rank));
    return r;
}
__device__ __forceinline__ void mbar_init(uint32_t addr, uint32_t cnt) {
    asm volatile("mbarrier.init.shared.b64 [%0], %1;" :: "r"(addr), "r"(cnt) : "memory");
}
__device__ __forceinline__ void mbar_arrive_expect(uint32_t addr, uint32_t tx) {
    asm volatile("mbarrier.arrive.expect_tx.shared.b64 _, [%0], %1;" :: "r"(addr), "r"(tx) : "memory");
}
__device__ __forceinline__ void mbar_arrive_local(uint32_t addr) {
    asm volatile("mbarrier.arrive.shared.b64 _, [%0];" :: "r"(addr) : "memory");
}
__device__ __forceinline__ void mbar_wait(uint32_t addr, uint32_t parity) {
    uint32_t done;
    asm volatile(
        "{\n\t.reg .pred p;\n\t"
        "mbarrier.try_wait.parity.acquire.cta.shared::cta.b64 p, [%1], %2;\n\t"
        "selp.b32 %0, 1, 0, p;\n\t}"
        : "=r"(done) : "r"(addr), "r"(parity) : "memory");
    if (!done) {
        asm volatile(
            "{\n\t.reg .pred P1;\n\t"
            "WL_%=:\n\t"
            "mbarrier.try_wait.parity.acquire.cta.shared::cta.b64 P1, [%0], %1, 0x989680;\n\t"
            "@P1 bra.uni WD_%=;\n\t"
            "bra.uni WL_%=;\n\t"
            "WD_%=:\n\t}"
            :: "r"(addr), "r"(parity) : "memory");
    }
}
__device__ __forceinline__ void bulk_s2s(uint32_t dst_cluster, uint32_t src_cta,
                                         uint32_t bytes, uint32_t mbar_cluster) {
    asm volatile(
        "cp.async.bulk.shared::cluster.shared::cta.mbarrier::complete_tx::bytes [%0], [%1], %2, [%3];"
        :: "r"(dst_cluster), "r"(src_cta), "r"(bytes), "r"(mbar_cluster) : "memory");
}
__device__ __forceinline__ void fence_proxy_async_() {
    asm volatile("fence.proxy.async.shared::cta;" ::: "memory");
}
__device__ __forceinline__ void cluster_sync_() {
    asm volatile("barrier.cluster.arrive.aligned;\n" ::: "memory");
    asm volatile("barrier.cluster.wait.aligned;\n" ::: "memory");
}
__device__ __forceinline__ uint32_t pk_bf2(float lo, float hi) {
    __nv_bfloat162 h = __floats2bfloat162_rn(lo, hi);
    return *(uint32_t*)&h;
}
__device__ __forceinline__ uint32_t lds_u32(uint32_t addr) {
    uint32_t v;
    asm volatile("ld.shared.u32 %0, [%1];" : "=r"(v) : "r"(addr));
    return v;
}
__device__ __forceinline__ void mma16816(float& c0, float& c1, float& c2, float& c3,
                                         uint32_t a0, uint32_t a1, uint32_t a2, uint32_t a3,
                                         uint32_t b0, uint32_t b1) {
    asm volatile(
        "mma.sync.aligned.m16n8k16.row.col.f32.bf16.bf16.f32 "
        "{%0,%1,%2,%3}, {%4,%5,%6,%7}, {%8,%9}, {%0,%1,%2,%3};"
        : "+f"(c0), "+f"(c1), "+f"(c2), "+f"(c3)
        : "r"(a0), "r"(a1), "r"(a2), "r"(a3), "r"(b0), "r"(b1));
}

// ---------------- prep kernels (unchanged math) ----------------
__global__ void prep_pi(const float* __restrict__ pi) {
    __shared__ float red[16];
    int tid = threadIdx.x;
    float v = pi[tid];
    float m = warp_max(v);
    if ((tid & 31) == 0) red[tid >> 5] = m;
    __syncthreads();
    float bm = red[0];
    #pragma unroll
    for (int i = 1; i < 16; i++) bm = fmaxf(bm, red[i]);
    __syncthreads();
    float e = expf(v - bm);
    float s = warp_sum(e);
    if ((tid & 31) == 0) red[tid >> 5] = s;
    __syncthreads();
    float bs = 0.f;
    #pragma unroll
    for (int i = 0; i < 16; i++) bs += red[i];
    g_expPi[tid] = e / bs;
}

__global__ void prep_A(const float* __restrict__ trans) {
    __shared__ float red[4];
    int p = blockIdx.x, tid = threadIdx.x;
    int lane = tid & 31, w = tid >> 5;
    float v[4];
    #pragma unroll
    for (int k = 0; k < 4; k++) v[k] = trans[(tid + 128 * k) * S + p];
    float m = fmaxf(fmaxf(v[0], v[1]), fmaxf(v[2], v[3]));
    m = warp_max(m);
    if (lane == 0) red[w] = m;
    __syncthreads();
    float bm = fmaxf(fmaxf(red[0], red[1]), fmaxf(red[2], red[3]));
    __syncthreads();
    float e[4], s = 0.f;
    #pragma unroll
    for (int k = 0; k < 4; k++) { e[k] = expf(v[k] - bm); s += e[k]; }
    s = warp_sum(s);
    if (lane == 0) red[w] = s;
    __syncthreads();
    float bs = red[0] + red[1] + red[2] + red[3];
    float inv = 1.0f / bs;
    #pragma unroll
    for (int k = 0; k < 4; k++) g_expA[(tid + 128 * k) * S + p] = e[k] * inv;
}

__global__ void prep_E(const float* __restrict__ emis) {
    __shared__ float red[8];
    int n = blockIdx.x, tid = threadIdx.x;
    int lane = tid & 31, w = tid >> 5;
    float v[4];
    #pragma unroll
    for (int k = 0; k < 4; k++) v[k] = emis[n * OBS + tid + 256 * k];
    float m = fmaxf(fmaxf(v[0], v[1]), fmaxf(v[2], v[3]));
    m = warp_max(m);
    if (lane == 0) red[w] = m;
    __syncthreads();
    float bm = red[0];
    #pragma unroll
    for (int i = 1; i < 8; i++) bm = fmaxf(bm, red[i]);
    __syncthreads();
    float e[4], s = 0.f;
    #pragma unroll
    for (int k = 0; k < 4; k++) { e[k] = expf(v[k] - bm); s += e[k]; }
    s = warp_sum(s);
    if (lane == 0) red[w] = s;
    __syncthreads();
    float bs = 0.f;
    #pragma unroll
    for (int i = 0; i < 8; i++) bs += red[i];
    float inv = 1.0f / bs;
    #pragma unroll
    for (int k = 0; k < 4; k++) g_expEt[(tid + 256 * k) * S + n] = e[k] * inv;
}

// ---------------- main: HMMA scaled forward, per-pair eager comm ----------------
__global__ void __cluster_dims__(CL, 1, 1) __launch_bounds__(NT, 1)
hmm_main(const int* __restrict__ x, const int* __restrict__ T, float* __restrict__ out) {
    extern __shared__ char smc[];
    int* Ts_sh = (int*)(smc + TS_OFF);

    const int tid  = threadIdx.x;
    const int wid  = tid >> 5, lane = tid & 31;
    const int rank = blockIdx.x & (CL - 1);
    const int b0   = (blockIdx.x >> 2) * BPC;
    const int nbase = rank * 128;

    const uint32_t smb  = (uint32_t)__cvta_generic_to_shared(smc);
    const uint32_t barF = smb + BAR_OFF;          // barF[buf][src] = barF + (buf*4+src)*8

    // fragment / role coords
    const int g  = lane >> 2, tg = lane & 3;
    const int kh = wid & 1;                       // k half
    const int m  = wid >> 1;                      // pair id 0..7
    const int mrow = m * 16;
    // epilogue coords (pair-local)
    const int b_ep = kh * 2 + (lane >> 4);        // 0..3
    const int n_ep = mrow + (lane & 15);

    // ---- barriers ----
    if (tid == 0) {
        #pragma unroll
        for (int s = 0; s < 2; s++)
            #pragma unroll
            for (int src = 0; src < CL; src++) {
                if (src == rank) {
                    mbar_init(barF + (s * 4 + src) * 8, 8);        // 8 pair arrivals
                } else {
                    mbar_init(barF + (s * 4 + src) * 8, 1);
                    mbar_arrive_expect(barF + (s * 4 + src) * 8, 8 * CHUNKB);
                }
            }
    }
    if (tid < BPC) Ts_sh[tid] = T[b0 + tid];

    // ---- v0 into buf0, pair-major chunks ----
    int xb0[BPC];
    #pragma unroll
    for (int b = 0; b < BPC; b++) xb0[b] = __ldg(&x[(b0 + b) * TMAXX]);
    for (int j = tid; j < 4 * 8 * BPC * 16; j += NT) {
        int s = j >> 9, mm = (j >> 6) & 7, b = (j >> 4) & 3, i = j & 15;
        int p = s * 128 + mm * 16 + i;
        float v = __ldg(&g_expEt[xb0[b] * S + p]) * __ldg(&g_expPi[p]);
        *(uint16_t*)(smc + B_OFF + s * SLICE2 + mm * CHUNKB + b * 32 + i * 2) =
            __bfloat16_as_ushort(__float2bfloat16(v));
    }
    if (tid < 128) {
        int s = tid >> 5, mm = (tid >> 2) & 7, b = tid & 3;
        float z = 0.f;
        for (int i = 0; i < 16; i++) {
            int p = s * 128 + mm * 16 + i;
            z += __ldg(&g_expEt[xb0[b] * S + p]) * __ldg(&g_expPi[p]);
        }
        *(float*)(smc + B_OFF + s * SLICE2 + mm * CHUNKB + 128 + b * 4) = z;
    }

    // ---- A fragments resident in registers (64 regs) ----
    uint32_t Ar[16][4];
    {
        const float* r0p = &g_expA[(nbase + mrow + g) * S + kh * 256 + tg * 2];
        const float* r1p = r0p + 8 * S;
        #pragma unroll
        for (int c = 0; c < 16; c++) {
            const float* a0 = r0p + c * 16;
            const float* a1 = r1p + c * 16;
            Ar[c][0] = pk_bf2(__ldg(a0),     __ldg(a0 + 1));
            Ar[c][1] = pk_bf2(__ldg(a1),     __ldg(a1 + 1));
            Ar[c][2] = pk_bf2(__ldg(a0 + 8), __ldg(a0 + 9));
            Ar[c][3] = pk_bf2(__ldg(a1 + 8), __ldg(a1 + 9));
        }
    }
    __syncthreads();
    cluster_sync_();   // barriers + v0 visible before any comm

    int maxT = 0;
    #pragma unroll
    for (int b = 0; b < BPC; b++) maxT = max(maxT, Ts_sh[b]);

    double off = 0.0;                // warp 0 lanes 0..3 (batch = lane)
    int cur = 0;
    uint32_t pf0 = 0, pf1 = 0;       // full parities (per warp, per buf)

    for (int t = 1; ; ++t) {
        const int nxt = cur ^ 1;

        // ---- prefetch E for epilogue ----
        int tt = t < TMAXX ? t : TMAXX - 1;
        int xbt = __ldg(&x[(b0 + b_ep) * TMAXX + tt]);
        float Ee = __ldg(&g_expEt[xbt * S + nbase + n_ep]);

        // ---- wait all 4 slice barriers for buf cur ----
        if (t > 1) {
            uint32_t par = cur ? pf1 : pf0;
            #pragma unroll
            for (int s = 0; s < CL; s++) mbar_wait(barF + (cur * 4 + s) * 8, par);
            if (cur) pf1 ^= 1; else pf0 ^= 1;
            // re-arm remote barriers of buf cur for reuse at t+2 (warp0 only).
            // Safe: peers cannot send t+2 data before receiving warp0's own
            // pair-0 chunk for t+1, which warp0 sends after this point.
            if (wid == 0 && lane >= 4 && lane < 8) {
                int src = lane - 4;
                if (src != rank) mbar_arrive_expect(barF + (cur * 4 + src) * 8, 8 * CHUNKB);
            }
        }

        // ---- z via butterfly over 32 chunk-zp float4s (every warp) ----
        float4 zp4;
        {
            const char* zpa = smc + B_OFF + cur * BUF2 + (lane >> 3) * SLICE2
                            + (lane & 7) * CHUNKB + 128;
            zp4 = *(const float4*)zpa;
            #pragma unroll
            for (int o = 16; o >= 1; o >>= 1) {
                zp4.x += __shfl_xor_sync(0xffffffffu, zp4.x, o);
                zp4.y += __shfl_xor_sync(0xffffffffu, zp4.y, o);
                zp4.z += __shfl_xor_sync(0xffffffffu, zp4.z, o);
                zp4.w += __shfl_xor_sync(0xffffffffu, zp4.w, o);
            }
        }
        // warp0: exact out/off bookkeeping
        if (wid == 0 && lane < 4) {
            float zl = (lane == 0) ? zp4.x : (lane == 1) ? zp4.y : (lane == 2) ? zp4.z : zp4.w;
            float lz = logf(zl);
            if (rank == 0 && Ts_sh[lane] == t) out[b0 + lane] = (float)(off + (double)lz);
            off += (double)lz;
        }
        if (t == maxT) break;
        float zb = (b_ep == 0) ? zp4.x : (b_ep == 1) ? zp4.y : (b_ep == 2) ? zp4.z : zp4.w;
        float rz = __fdividef(1.f, zb);

        // ---- MMA: this warp's k half, two accumulator chains ----
        {
            const uint32_t vwb = smb + B_OFF + cur * BUF2 + (kh * 2) * SLICE2 + g * 32 + tg * 4;
            float c0 = 0.f, c1 = 0.f, c2 = 0.f, c3 = 0.f;
            float d0 = 0.f, d1 = 0.f, d2 = 0.f, d3 = 0.f;
            #pragma unroll
            for (int c = 0; c < 16; c += 2) {
                uint32_t a0 = vwb + (uint32_t)((c >> 3) * SLICE2 + (c & 7) * CHUNKB);
                uint32_t a1 = vwb + (uint32_t)(((c + 1) >> 3) * SLICE2 + ((c + 1) & 7) * CHUNKB);
                uint32_t p0 = lds_u32(a0), p1 = lds_u32(a0 + 16);
                uint32_t q0 = lds_u32(a1), q1 = lds_u32(a1 + 16);
                mma16816(c0, c1, c2, c3, Ar[c][0], Ar[c][1], Ar[c][2], Ar[c][3], p0, p1);
                mma16816(d0, d1, d2, d3, Ar[c + 1][0], Ar[c + 1][1], Ar[c + 1][2], Ar[c + 1][3], q0, q1);
            }
            c0 += d0; c1 += d1; c2 += d2; c3 += d3;
            // CP[pair][kh][n16][b4], batch cols 0-3 only (tg<2)
            if (tg < 2) {
                uint32_t cpb = (uint32_t)(CP_OFF + m * 512 + kh * 256 + tg * 8);
                *(float2*)(smc + cpb + g * 16)       = make_float2(c0, c1);
                *(float2*)(smc + cpb + (g + 8) * 16) = make_float2(c2, c3);
            }
        }
        asm volatile("bar.sync %0, 64;" :: "r"(2 + m) : "memory");   // pair combine

        // ---- epilogue: combine k halves, scale, store local chunk, zp ----
        const uint32_t chunk = smb + B_OFF + nxt * BUF2 + rank * SLICE2 + m * CHUNKB;
        {
            uint32_t cpi = (uint32_t)(CP_OFF + m * 512 + (lane & 15) * 16 + b_ep * 4);
            float c = *(float*)(smc + cpi) + *(float*)(smc + cpi + 256);
            float w = c * Ee * rz;
            *(uint16_t*)(smc + (chunk - smb) + b_ep * 32 + (lane & 15) * 2) =
                __bfloat16_as_ushort(__float2bfloat16(w));
            float zs = w;
            #pragma unroll
            for (int o = 1; o <= 8; o <<= 1) zs += __shfl_xor_sync(0xffffffffu, zs, o);
            if ((lane & 15) == 0)
                *(float*)(smc + (chunk - smb) + 128 + b_ep * 4) = zs;
        }
        asm volatile("bar.sync %0, 64;" :: "r"(2 + m) : "memory");   // chunk complete

        // ---- pair leader: eager comm (3 peers) + local arrive ----
        if (kh == 0 && lane == 0) {
            fence_proxy_async_();
            #pragma unroll
            for (int r = 0; r < CL; r++) {
                if (r == rank) continue;
                bulk_s2s(mapa_u32(chunk, r), chunk, CHUNKB,
                         mapa_u32(barF + (nxt * 4 + rank) * 8, r));
            }
            mbar_arrive_local(barF + (nxt * 4 + rank) * 8);
        }
        cur = nxt;
    }

    cluster_sync_();   // drain in-flight copies before exit
}

// ---------------- launch ----------------
extern "C" void kernel_launch(void* const* d_in, const int* in_sizes, int n_in,
                              void* d_out, int out_size) {
    const int*   x     = (const int*)d_in[0];
    const int*   T     = (const int*)d_in[1];
    const float* pi    = (const float*)d_in[2];
    const float* trans = (const float*)d_in[3];
    const float* emis  = (const float*)d_in[4];
    float* out = (float*)d_out;

    cudaFuncSetAttribute(hmm_main, cudaFuncAttributeMaxDynamicSharedMemorySize, SMEM_BYTES);

    prep_pi<<<1, S>>>(pi);
    prep_A<<<S, 128>>>(trans);
    prep_E<<<S, 256>>>(emis);
    hmm_main<<<NCTAS, NT, SMEM_BYTES>>>(x, T, out);
}

// round 14
// speedup vs baseline: 1.2604x; 1.2604x over previous
#include <cuda_runtime.h>
#include <cuda_bf16.h>
#include <cstdint>

#define S       512
#define TMAXX   2048
#define OBS     1024
#define CL      4
#define BPC     4
#define NT      512
#define NCTAS   128

// B slice: 8 rows x 272B; rows 0-3 = v bf16[128], zp float4 at byte 1088
#define BROWB   272
#define SLICEB  2176
#define BUF_B   8704
#define ZPOFF   1088

// smem layout (bytes)
#define B_OFF   0                      // [2][4][SLICEB] = 17408
#define CP_OFF  17408                  // cp[8 pair][2 kh][16 n][4 b] f32 = 4096
#define ZR_OFF  (CP_OFF + 4096)        // zr[8 pair][4 b] f32 = 128
#define TS_OFF  (ZR_OFF + 128)         // Ts[4]
#define BAR_OFF (TS_OFF + 16)          // barF[2] = 16B
#define SMEM_BYTES (BAR_OFF + 64)

// ---------------- device tables ----------------
__device__ float g_expA[S * S];      // [n][p]
__device__ float g_expEt[OBS * S];   // [o][n]
__device__ float g_expPi[S];

// ---------------- helpers ----------------
__device__ __forceinline__ float warp_max(float v) {
    #pragma unroll
    for (int o = 16; o; o >>= 1) v = fmaxf(v, __shfl_xor_sync(0xffffffffu, v, o));
    return v;
}
__device__ __forceinline__ float warp_sum(float v) {
    #pragma unroll
    for (int o = 16; o; o >>= 1) v += __shfl_xor_sync(0xffffffffu, v, o);
    return v;
}
__device__ __forceinline__ uint32_t mapa_u32(uint32_t addr, int rank) {
    uint32_t r;
    asm("mapa.shared::cluster.u32 %0, %1, %2;" : "=r"(r) : "r"(addr), "r"(rank));
    return r;
}
__device__ __forceinline__ void mbar_init(uint32_t addr, uint32_t cnt) {
    asm volatile("mbarrier.init.shared.b64 [%0], %1;" :: "r"(addr), "r"(cnt) : "memory");
}
__device__ __forceinline__ void mbar_arrive_expect(uint32_t addr, uint32_t tx) {
    asm volatile("mbarrier.arrive.expect_tx.shared.b64 _, [%0], %1;" :: "r"(addr), "r"(tx) : "memory");
}
__device__ __forceinline__ void mbar_arrive_local(uint32_t addr) {
    asm volatile("mbarrier.arrive.shared.b64 _, [%0];" :: "r"(addr) : "memory");
}
__device__ __forceinline__ void mbar_wait(uint32_t addr, uint32_t parity) {
    uint32_t done;
    asm volatile(
        "{\n\t.reg .pred p;\n\t"
        "mbarrier.try_wait.parity.acquire.cta.shared::cta.b64 p, [%1], %2;\n\t"
        "selp.b32 %0, 1, 0, p;\n\t}"
        : "=r"(done) : "r"(addr), "r"(parity) : "memory");
    if (!done) {
        asm volatile(
            "{\n\t.reg .pred P1;\n\t"
            "WL_%=:\n\t"
            "mbarrier.try_wait.parity.acquire.cta.shared::cta.b64 P1, [%0], %1, 0x989680;\n\t"
            "@P1 bra.uni WD_%=;\n\t"
            "bra.uni WL_%=;\n\t"
            "WD_%=:\n\t}"
            :: "r"(addr), "r"(parity) : "memory");
    }
}
__device__ __forceinline__ void bulk_s2s(uint32_t dst_cluster, uint32_t src_cta,
                                         uint32_t bytes, uint32_t mbar_cluster) {
    asm volatile(
        "cp.async.bulk.shared::cluster.shared::cta.mbarrier::complete_tx::bytes [%0], [%1], %2, [%3];"
        :: "r"(dst_cluster), "r"(src_cta), "r"(bytes), "r"(mbar_cluster) : "memory");
}
__device__ __forceinline__ void fence_proxy_async_() {
    asm volatile("fence.proxy.async.shared::cta;" ::: "memory");
}
__device__ __forceinline__ void cluster_sync_() {
    asm volatile("barrier.cluster.arrive.aligned;\n" ::: "memory");
    asm volatile("barrier.cluster.wait.aligned;\n" ::: "memory");
}
__device__ __forceinline__ uint32_t pk_bf2(float lo, float hi) {
    __nv_bfloat162 h = __floats2bfloat162_rn(lo, hi);
    return *(uint32_t*)&h;
}
__device__ __forceinline__ uint32_t lds_u32(uint32_t addr) {
    uint32_t v;
    asm volatile("ld.shared.u32 %0, [%1];" : "=r"(v) : "r"(addr));
    return v;
}
__device__ __forceinline__ void mma16816(float& c0, float& c1, float& c2, float& c3,
                                         uint32_t a0, uint32_t a1, uint32_t a2, uint32_t a3,
                                         uint32_t b0, uint32_t b1) {
    asm volatile(
        "mma.sync.aligned.m16n8k16.row.col.f32.bf16.bf16.f32 "
        "{%0,%1,%2,%3}, {%4,%5,%6,%7}, {%8,%9}, {%0,%1,%2,%3};"
        : "+f"(c0), "+f"(c1), "+f"(c2), "+f"(c3)
        : "r"(a0), "r"(a1), "r"(a2), "r"(a3), "r"(b0), "r"(b1));
}

// ---------------- prep kernels (unchanged math) ----------------
__global__ void prep_pi(const float* __restrict__ pi) {
    __shared__ float red[16];
    int tid = threadIdx.x;
    float v = pi[tid];
    float m = warp_max(v);
    if ((tid & 31) == 0) red[tid >> 5] = m;
    __syncthreads();
    float bm = red[0];
    #pragma unroll
    for (int i = 1; i < 16; i++) bm = fmaxf(bm, red[i]);
    __syncthreads();
    float e = expf(v - bm);
    float s = warp_sum(e);
    if ((tid & 31) == 0) red[tid >> 5] = s;
    __syncthreads();
    float bs = 0.f;
    #pragma unroll
    for (int i = 0; i < 16; i++) bs += red[i];
    g_expPi[tid] = e / bs;
}

__global__ void prep_A(const float* __restrict__ trans) {
    __shared__ float red[4];
    int p = blockIdx.x, tid = threadIdx.x;
    int lane = tid & 31, w = tid >> 5;
    float v[4];
    #pragma unroll
    for (int k = 0; k < 4; k++) v[k] = trans[(tid + 128 * k) * S + p];
    float m = fmaxf(fmaxf(v[0], v[1]), fmaxf(v[2], v[3]));
    m = warp_max(m);
    if (lane == 0) red[w] = m;
    __syncthreads();
    float bm = fmaxf(fmaxf(red[0], red[1]), fmaxf(red[2], red[3]));
    __syncthreads();
    float e[4], s = 0.f;
    #pragma unroll
    for (int k = 0; k < 4; k++) { e[k] = expf(v[k] - bm); s += e[k]; }
    s = warp_sum(s);
    if (lane == 0) red[w] = s;
    __syncthreads();
    float bs = red[0] + red[1] + red[2] + red[3];
    float inv = 1.0f / bs;
    #pragma unroll
    for (int k = 0; k < 4; k++) g_expA[(tid + 128 * k) * S + p] = e[k] * inv;
}

__global__ void prep_E(const float* __restrict__ emis) {
    __shared__ float red[8];
    int n = blockIdx.x, tid = threadIdx.x;
    int lane = tid & 31, w = tid >> 5;
    float v[4];
    #pragma unroll
    for (int k = 0; k < 4; k++) v[k] = emis[n * OBS + tid + 256 * k];
    float m = fmaxf(fmaxf(v[0], v[1]), fmaxf(v[2], v[3]));
    m = warp_max(m);
    if (lane == 0) red[w] = m;
    __syncthreads();
    float bm = red[0];
    #pragma unroll
    for (int i = 1; i < 8; i++) bm = fmaxf(bm, red[i]);
    __syncthreads();
    float e[4], s = 0.f;
    #pragma unroll
    for (int k = 0; k < 4; k++) { e[k] = expf(v[k] - bm); s += e[k]; }
    s = warp_sum(s);
    if (lane == 0) red[w] = s;
    __syncthreads();
    float bs = 0.f;
    #pragma unroll
    for (int i = 0; i < 8; i++) bs += red[i];
    float inv = 1.0f / bs;
    #pragma unroll
    for (int k = 0; k < 4; k++) g_expEt[(tid + 256 * k) * S + n] = e[k] * inv;
}

// ---------------- main: HMMA scaled forward, single-barrier pipeline ----------------
__global__ void __cluster_dims__(CL, 1, 1) __launch_bounds__(NT, 1)
hmm_main(const int* __restrict__ x, const int* __restrict__ T, float* __restrict__ out) {
    extern __shared__ char smc[];
    float* ZRf = (float*)(smc + ZR_OFF);
    int* Ts_sh = (int*)(smc + TS_OFF);

    const int tid  = threadIdx.x;
    const int wid  = tid >> 5, lane = tid & 31;
    const int rank = blockIdx.x & (CL - 1);
    const int b0   = (blockIdx.x >> 2) * BPC;
    const int nbase = rank * 128;

    const uint32_t smb  = (uint32_t)__cvta_generic_to_shared(smc);
    const uint32_t barF = smb + BAR_OFF;          // barF[buf] = barF + buf*8

    // fragment / role coords
    const int g  = lane >> 2, tg = lane & 3;
    const int kh = wid & 1;                       // k half
    const int m  = wid >> 1;                      // pair id 0..7
    const int mrow = m * 16;
    // epilogue coords (pair-local)
    const int b_ep = kh * 2 + (lane >> 4);        // 0..3
    const int n_ep = mrow + (lane & 15);

    // ---- barriers: one per buffer; count=2 (arm + local), tx = 3 slices ----
    if (tid == 0) {
        mbar_init(barF + 0, 2);
        mbar_init(barF + 8, 2);
        mbar_arrive_expect(barF + 0, 3 * SLICEB);
        mbar_arrive_expect(barF + 8, 3 * SLICEB);
    }
    if (tid < BPC) Ts_sh[tid] = T[b0 + tid];

    // ---- zero both B buffers ----
    for (int j = tid; j < 2 * BUF_B / 4; j += NT) ((uint32_t*)smc)[B_OFF / 4 + j] = 0u;
    __syncthreads();

    // ---- v0: all 4 slices locally, rows b<4 ----
    int xb0[BPC];
    #pragma unroll
    for (int b = 0; b < BPC; b++) xb0[b] = __ldg(&x[(b0 + b) * TMAXX]);
    for (int j = tid; j < 4 * BPC * 128; j += NT) {
        int s = j >> 9, b = (j >> 7) & 3, pl = j & 127;
        int p = s * 128 + pl;
        float v = __ldg(&g_expEt[xb0[b] * S + p]) * __ldg(&g_expPi[p]);
        *(uint16_t*)(smc + B_OFF + s * SLICEB + b * BROWB + pl * 2) =
            __bfloat16_as_ushort(__float2bfloat16(v));
    }
    // zp for buffer 0 (exact f32) at slice offset ZPOFF
    if (tid < 16) {
        int s = tid >> 2, b = tid & 3;
        float z = 0.f;
        for (int pl = 0; pl < 128; pl++) {
            int p = s * 128 + pl;
            z += __ldg(&g_expEt[xb0[b] * S + p]) * __ldg(&g_expPi[p]);
        }
        *(float*)(smc + B_OFF + s * SLICEB + ZPOFF + b * 4) = z;
    }

    // ---- A fragments resident in registers (64 regs) ----
    uint32_t Ar[16][4];
    {
        const float* r0p = &g_expA[(nbase + mrow + g) * S + kh * 256 + tg * 2];
        const float* r1p = r0p + 8 * S;
        #pragma unroll
        for (int c = 0; c < 16; c++) {
            const float* a0 = r0p + c * 16;
            const float* a1 = r1p + c * 16;
            Ar[c][0] = pk_bf2(__ldg(a0),     __ldg(a0 + 1));
            Ar[c][1] = pk_bf2(__ldg(a1),     __ldg(a1 + 1));
            Ar[c][2] = pk_bf2(__ldg(a0 + 8), __ldg(a0 + 9));
            Ar[c][3] = pk_bf2(__ldg(a1 + 8), __ldg(a1 + 9));
        }
    }
    __syncthreads();
    cluster_sync_();   // barriers + v0 visible before any comm

    int maxT = 0;
    #pragma unroll
    for (int b = 0; b < BPC; b++) maxT = max(maxT, Ts_sh[b]);

    double off = 0.0;                // warp 0 lanes 0..3 (batch = lane)
    int cur = 0;
    uint32_t pf0 = 0, pf1 = 0;       // full parities (per warp, per buf)

    for (int t = 1; ; ++t) {
        const int nxt = cur ^ 1;

        // ---- prefetch E for epilogue ----
        int tt = t < TMAXX ? t : TMAXX - 1;
        int xbt = __ldg(&x[(b0 + b_ep) * TMAXX + tt]);
        float Ee = __ldg(&g_expEt[xbt * S + nbase + n_ep]);

        // ---- single wait for buf cur; warp0 re-arms immediately ----
        if (t > 1) {
            mbar_wait(barF + cur * 8, cur ? pf1 : pf0);
            if (cur) pf1 ^= 1; else pf0 ^= 1;
            // re-arm for reuse at t+2 (arrival 1 of next phase). Safe: peers
            // can't send t+2 data before receiving my t+1 slice, which warp0
            // sends after this point.
            if (wid == 0 && lane == 0)
                mbar_arrive_expect(barF + cur * 8, 3 * SLICEB);
        }

        // ---- MMA first (2 accumulator chains, even/odd k-chunks) ----
        float c0 = 0.f, c1 = 0.f, c2 = 0.f, c3 = 0.f;
        {
            const uint32_t vwb = smb + B_OFF + cur * BUF_B + kh * (2 * SLICEB)
                               + g * BROWB + tg * 4;
            float d0 = 0.f, d1 = 0.f, d2 = 0.f, d3 = 0.f;
            #pragma unroll
            for (int c = 0; c < 16; c += 2) {
                uint32_t boffA = (uint32_t)((c >> 3) * SLICEB + (c & 7) * 32);
                uint32_t boffB = (uint32_t)(((c + 1) >> 3) * SLICEB + ((c + 1) & 7) * 32);
                uint32_t p0 = lds_u32(vwb + boffA), p1 = lds_u32(vwb + boffA + 16);
                uint32_t q0 = lds_u32(vwb + boffB), q1 = lds_u32(vwb + boffB + 16);
                mma16816(c0, c1, c2, c3, Ar[c][0], Ar[c][1], Ar[c][2], Ar[c][3], p0, p1);
                mma16816(d0, d1, d2, d3, Ar[c + 1][0], Ar[c + 1][1], Ar[c + 1][2], Ar[c + 1][3], q0, q1);
            }
            c0 += d0; c1 += d1; c2 += d2; c3 += d3;
        }

        // ---- z / rz / bookkeeping (issues under HMMA shadow) ----
        float rzv = 0.f;
        {
            float z4 = 0.f;
            if (lane < 16)
                z4 = *(float*)(smc + B_OFF + cur * BUF_B + (lane >> 2) * SLICEB + ZPOFF + (lane & 3) * 4);
            z4 += __shfl_xor_sync(0xffffffffu, z4, 4);
            z4 += __shfl_xor_sync(0xffffffffu, z4, 8);   // lanes 0-15: total z for b=lane&3
            if (wid == 0 && lane < 4) {
                float lz = logf(z4);
                if (rank == 0 && Ts_sh[lane] == t) out[b0 + lane] = (float)(off + (double)lz);
                off += (double)lz;
            }
            if (lane < 4) rzv = __fdividef(1.f, z4);
        }
        if (t == maxT) break;
        float rz = __shfl_sync(0xffffffffu, rzv, b_ep);

        // ---- store CP partials (batch cols 0-3 only; tg<2) ----
        if (tg < 2) {
            uint32_t cpb = (uint32_t)(CP_OFF + m * 512 + kh * 256 + tg * 8);
            *(float2*)(smc + cpb + g * 16)       = make_float2(c0, c1);
            *(float2*)(smc + cpb + (g + 8) * 16) = make_float2(c2, c3);
        }
        asm volatile("bar.sync %0, 64;" :: "r"(2 + m) : "memory");   // pair combine

        // ---- epilogue: combine k halves, scale, store local slice, z partial ----
        {
            uint32_t cpi = (uint32_t)(CP_OFF + m * 512 + (lane & 15) * 16 + b_ep * 4);
            float c = *(float*)(smc + cpi) + *(float*)(smc + cpi + 256);
            float w = c * Ee * rz;
            *(uint16_t*)(smc + B_OFF + nxt * BUF_B + rank * SLICEB + b_ep * BROWB + (lane & 15) * 2 + (mrow * 2)) =
                __bfloat16_as_ushort(__float2bfloat16(w));
            float zs = w;
            #pragma unroll
            for (int o = 1; o <= 8; o <<= 1) zs += __shfl_xor_sync(0xffffffffu, zs, o);
            if ((lane & 15) == 0) ZRf[m * 4 + b_ep] = zs;
        }

        // ---- main barrier: only warp0 blocks; others run ahead ----
        if (wid != 0) {
            asm volatile("bar.arrive 1, %0;" :: "r"(NT) : "memory");
        } else {
            asm volatile("bar.sync 1, %0;" :: "r"(NT) : "memory");
            const uint32_t slb = smb + B_OFF + nxt * BUF_B + rank * SLICEB;
            // zp totals over 8 pairs (ZRf has exactly 32 entries: [m][b])
            float zr = ZRf[lane];
            zr += __shfl_xor_sync(0xffffffffu, zr, 4);
            zr += __shfl_xor_sync(0xffffffffu, zr, 8);
            zr += __shfl_xor_sync(0xffffffffu, zr, 16);
            if (lane < 4) *(float*)(smc + (slb - smb) + ZPOFF + lane * 4) = zr;
            __syncwarp();
            if (lane == 0) {
                fence_proxy_async_();
                #pragma unroll
                for (int r = 0; r < CL; r++) {
                    if (r == rank) continue;
                    bulk_s2s(mapa_u32(slb, r), slb, SLICEB,
                             mapa_u32(barF + nxt * 8, r));
                }
                mbar_arrive_local(barF + nxt * 8);   // arrival 2: local slice + zp ready
            }
        }
        cur = nxt;
    }

    cluster_sync_();   // drain in-flight copies before exit
}

// ---------------- launch ----------------
extern "C" void kernel_launch(void* const* d_in, const int* in_sizes, int n_in,
                              void* d_out, int out_size) {
    const int*   x     = (const int*)d_in[0];
    const int*   T     = (const int*)d_in[1];
    const float* pi    = (const float*)d_in[2];
    const float* trans = (const float*)d_in[3];
    const float* emis  = (const float*)d_in[4];
    float* out = (float*)d_out;

    cudaFuncSetAttribute(hmm_main, cudaFuncAttributeMaxDynamicSharedMemorySize, SMEM_BYTES);

    prep_pi<<<1, S>>>(pi);
    prep_A<<<S, 128>>>(trans);
    prep_E<<<S, 256>>>(emis);
    hmm_main<<<NCTAS, NT, SMEM_BYTES>>>(x, T, out);
}

// round 16
// speedup vs baseline: 1.2771x; 1.0133x over previous
#include <cuda_runtime.h>
#include <cuda_bf16.h>
#include <cstdint>

#define S       512
#define TMAXX   2048
#define OBS     1024
#define CL      4
#define BPC     4
#define NT      256
#define NCTAS   128

// B slice: 4 rows x 272B (v bf16[128]) ; zp float4 at byte 1088
#define BROWB   272
#define SLICEB  2176
#define BUF_B   8704
#define ZPOFF   1088

// smem layout (bytes)
#define B_OFF   0                      // [2][4][SLICEB] = 17408
#define ZR_OFF  17408                  // zr[8 warp][4 b] f32 = 128
#define TS_OFF  (ZR_OFF + 128)         // Ts[4]
#define BAR_OFF (TS_OFF + 16)          // barF[2] = 16B
#define SMEM_BYTES (BAR_OFF + 64)

// ---------------- device tables ----------------
__device__ float g_expA[S * S];      // [n][p]
__device__ float g_expEt[OBS * S];   // [o][n]
__device__ float g_expPi[S];

// ---------------- helpers ----------------
__device__ __forceinline__ float warp_max(float v) {
    #pragma unroll
    for (int o = 16; o; o >>= 1) v = fmaxf(v, __shfl_xor_sync(0xffffffffu, v, o));
    return v;
}
__device__ __forceinline__ float warp_sum(float v) {
    #pragma unroll
    for (int o = 16; o; o >>= 1) v += __shfl_xor_sync(0xffffffffu, v, o);
    return v;
}
__device__ __forceinline__ uint32_t mapa_u32(uint32_t addr, int rank) {
    uint32_t r;
    asm("mapa.shared::cluster.u32 %0, %1, %2;" : "=r"(r) : "r"(addr), "r"(rank));
    return r;
}
__device__ __forceinline__ void mbar_init(uint32_t addr, uint32_t cnt) {
    asm volatile("mbarrier.init.shared.b64 [%0], %1;" :: "r"(addr), "r"(cnt) : "memory");
}
__device__ __forceinline__ void mbar_arrive_expect(uint32_t addr, uint32_t tx) {
    asm volatile("mbarrier.arrive.expect_tx.shared.b64 _, [%0], %1;" :: "r"(addr), "r"(tx) : "memory");
}
__device__ __forceinline__ void mbar_arrive_local(uint32_t addr) {
    asm volatile("mbarrier.arrive.shared.b64 _, [%0];" :: "r"(addr) : "memory");
}
__device__ __forceinline__ void mbar_wait(uint32_t addr, uint32_t parity) {
    uint32_t done;
    asm volatile(
        "{\n\t.reg .pred p;\n\t"
        "mbarrier.try_wait.parity.acquire.cta.shared::cta.b64 p, [%1], %2;\n\t"
        "selp.b32 %0, 1, 0, p;\n\t}"
        : "=r"(done) : "r"(addr), "r"(parity) : "memory");
    if (!done) {
        asm volatile(
            "{\n\t.reg .pred P1;\n\t"
            "WL_%=:\n\t"
            "mbarrier.try_wait.parity.acquire.cta.shared::cta.b64 P1, [%0], %1, 0x989680;\n\t"
            "@P1 bra.uni WD_%=;\n\t"
            "bra.uni WL_%=;\n\t"
            "WD_%=:\n\t}"
            :: "r"(addr), "r"(parity) : "memory");
    }
}
__device__ __forceinline__ void bulk_s2s(uint32_t dst_cluster, uint32_t src_cta,
                                         uint32_t bytes, uint32_t mbar_cluster) {
    asm volatile(
        "cp.async.bulk.shared::cluster.shared::cta.mbarrier::complete_tx::bytes [%0], [%1], %2, [%3];"
        :: "r"(dst_cluster), "r"(src_cta), "r"(bytes), "r"(mbar_cluster) : "memory");
}
__device__ __forceinline__ void fence_proxy_async_() {
    asm volatile("fence.proxy.async.shared::cta;" ::: "memory");
}
__device__ __forceinline__ void cluster_sync_() {
    asm volatile("barrier.cluster.arrive.aligned;\n" ::: "memory");
    asm volatile("barrier.cluster.wait.aligned;\n" ::: "memory");
}
__device__ __forceinline__ uint32_t pk_bf2(float lo, float hi) {
    __nv_bfloat162 h = __floats2bfloat162_rn(lo, hi);
    return *(uint32_t*)&h;
}
__device__ __forceinline__ uint32_t lds_u32(uint32_t addr) {
    uint32_t v;
    asm volatile("ld.shared.u32 %0, [%1];" : "=r"(v) : "r"(addr));
    return v;
}
__device__ __forceinline__ void mma16816(float& c0, float& c1, float& c2, float& c3,
                                         uint32_t a0, uint32_t a1, uint32_t a2, uint32_t a3,
                                         uint32_t b0, uint32_t b1) {
    asm volatile(
        "mma.sync.aligned.m16n8k16.row.col.f32.bf16.bf16.f32 "
        "{%0,%1,%2,%3}, {%4,%5,%6,%7}, {%8,%9}, {%0,%1,%2,%3};"
        : "+f"(c0), "+f"(c1), "+f"(c2), "+f"(c3)
        : "r"(a0), "r"(a1), "r"(a2), "r"(a3), "r"(b0), "r"(b1));
}

// ---------------- prep kernels (unchanged math) ----------------
__global__ void prep_pi(const float* __restrict__ pi) {
    __shared__ float red[16];
    int tid = threadIdx.x;
    float v = pi[tid];
    float m = warp_max(v);
    if ((tid & 31) == 0) red[tid >> 5] = m;
    __syncthreads();
    float bm = red[0];
    #pragma unroll
    for (int i = 1; i < 16; i++) bm = fmaxf(bm, red[i]);
    __syncthreads();
    float e = expf(v - bm);
    float s = warp_sum(e);
    if ((tid & 31) == 0) red[tid >> 5] = s;
    __syncthreads();
    float bs = 0.f;
    #pragma unroll
    for (int i = 0; i < 16; i++) bs += red[i];
    g_expPi[tid] = e / bs;
}

__global__ void prep_A(const float* __restrict__ trans) {
    __shared__ float red[4];
    int p = blockIdx.x, tid = threadIdx.x;
    int lane = tid & 31, w = tid >> 5;
    float v[4];
    #pragma unroll
    for (int k = 0; k < 4; k++) v[k] = trans[(tid + 128 * k) * S + p];
    float m = fmaxf(fmaxf(v[0], v[1]), fmaxf(v[2], v[3]));
    m = warp_max(m);
    if (lane == 0) red[w] = m;
    __syncthreads();
    float bm = fmaxf(fmaxf(red[0], red[1]), fmaxf(red[2], red[3]));
    __syncthreads();
    float e[4], s = 0.f;
    #pragma unroll
    for (int k = 0; k < 4; k++) { e[k] = expf(v[k] - bm); s += e[k]; }
    s = warp_sum(s);
    if (lane == 0) red[w] = s;
    __syncthreads();
    float bs = red[0] + red[1] + red[2] + red[3];
    float inv = 1.0f / bs;
    #pragma unroll
    for (int k = 0; k < 4; k++) g_expA[(tid + 128 * k) * S + p] = e[k] * inv;
}

__global__ void prep_E(const float* __restrict__ emis) {
    __shared__ float red[8];
    int n = blockIdx.x, tid = threadIdx.x;
    int lane = tid & 31, w = tid >> 5;
    float v[4];
    #pragma unroll
    for (int k = 0; k < 4; k++) v[k] = emis[n * OBS + tid + 256 * k];
    float m = fmaxf(fmaxf(v[0], v[1]), fmaxf(v[2], v[3]));
    m = warp_max(m);
    if (lane == 0) red[w] = m;
    __syncthreads();
    float bm = red[0];
    #pragma unroll
    for (int i = 1; i < 8; i++) bm = fmaxf(bm, red[i]);
    __syncthreads();
    float e[4], s = 0.f;
    #pragma unroll
    for (int k = 0; k < 4; k++) { e[k] = expf(v[k] - bm); s += e[k]; }
    s = warp_sum(s);
    if (lane == 0) red[w] = s;
    __syncthreads();
    float bs = 0.f;
    #pragma unroll
    for (int i = 0; i < 8; i++) bs += red[i];
    float inv = 1.0f / bs;
    #pragma unroll
    for (int k = 0; k < 4; k++) g_expEt[(tid + 256 * k) * S + n] = e[k] * inv;
}

// ---------------- main: HMMA full-K per warp, no combine ----------------
__global__ void __cluster_dims__(CL, 1, 1) __launch_bounds__(NT, 1)
hmm_main(const int* __restrict__ x, const int* __restrict__ T, float* __restrict__ out) {
    extern __shared__ char smc[];
    float* ZRf = (float*)(smc + ZR_OFF);
    int* Ts_sh = (int*)(smc + TS_OFF);

    const int tid  = threadIdx.x;
    const int wid  = tid >> 5, lane = tid & 31;
    const int rank = blockIdx.x & (CL - 1);
    const int b0   = (blockIdx.x >> 2) * BPC;
    const int nbase = rank * 128;

    const uint32_t smb  = (uint32_t)__cvta_generic_to_shared(smc);
    const uint32_t barF = smb + BAR_OFF;          // barF[buf] = barF + buf*8

    // fragment coords: warp wid -> rows mrow..mrow+15, full K
    const int g  = lane >> 2, tg = lane & 3;
    const int mrow = wid * 16;
    const int n0 = nbase + mrow + g;              // global rows n0, n0+8
    const int bA = 2 * tg, bB = 2 * tg + 1;       // batches (real iff tg<2)
    const int bAc = bA & 3, bBc = bB & 3;         // clamped lane indices for shfl

    // ---- barriers: one per buffer; count=2 (arm + local), tx = 3 slices ----
    if (tid == 0) {
        mbar_init(barF + 0, 2);
        mbar_init(barF + 8, 2);
        mbar_arrive_expect(barF + 0, 3 * SLICEB);
        mbar_arrive_expect(barF + 8, 3 * SLICEB);
    }
    if (tid < BPC) Ts_sh[tid] = T[b0 + tid];

    // ---- zero both B buffers ----
    for (int j = tid; j < 2 * BUF_B / 4; j += NT) ((uint32_t*)smc)[B_OFF / 4 + j] = 0u;
    __syncthreads();

    // ---- v0: all 4 slices locally, rows b<4 ----
    int xb0[BPC];
    #pragma unroll
    for (int b = 0; b < BPC; b++) xb0[b] = __ldg(&x[(b0 + b) * TMAXX]);
    for (int j = tid; j < 4 * BPC * 128; j += NT) {
        int s = j >> 9, b = (j >> 7) & 3, pl = j & 127;
        int p = s * 128 + pl;
        float v = __ldg(&g_expEt[xb0[b] * S + p]) * __ldg(&g_expPi[p]);
        *(uint16_t*)(smc + B_OFF + s * SLICEB + b * BROWB + pl * 2) =
            __bfloat16_as_ushort(__float2bfloat16(v));
    }
    // zp for buffer 0 (exact f32) at slice offset ZPOFF
    if (tid < 16) {
        int s = tid >> 2, b = tid & 3;
        float z = 0.f;
        for (int pl = 0; pl < 128; pl++) {
            int p = s * 128 + pl;
            z += __ldg(&g_expEt[xb0[b] * S + p]) * __ldg(&g_expPi[p]);
        }
        *(float*)(smc + B_OFF + s * SLICEB + ZPOFF + b * 4) = z;
    }

    // ---- A fragments resident in registers: FULL K (128 regs) ----
    uint32_t Ar[32][4];
    {
        const float* r0p = &g_expA[(nbase + mrow + g) * S + tg * 2];
        const float* r1p = r0p + 8 * S;
        #pragma unroll
        for (int c = 0; c < 32; c++) {
            const float* a0 = r0p + c * 16;
            const float* a1 = r1p + c * 16;
            Ar[c][0] = pk_bf2(__ldg(a0),     __ldg(a0 + 1));
            Ar[c][1] = pk_bf2(__ldg(a1),     __ldg(a1 + 1));
            Ar[c][2] = pk_bf2(__ldg(a0 + 8), __ldg(a0 + 9));
            Ar[c][3] = pk_bf2(__ldg(a1 + 8), __ldg(a1 + 9));
        }
    }
    __syncthreads();
    cluster_sync_();   // barriers + v0 visible before any comm

    int maxT = 0;
    #pragma unroll
    for (int b = 0; b < BPC; b++) maxT = max(maxT, Ts_sh[b]);

    double off = 0.0;                // warp 0 lanes 0..3 (batch = lane)
    int cur = 0;
    uint32_t pf0 = 0, pf1 = 0;       // full parities

    for (int t = 1; ; ++t) {
        const int nxt = cur ^ 1;

        // ---- prefetch E for epilogue (tg<2 lanes; 2 rows x 2 batches) ----
        float E00 = 0.f, E01 = 0.f, E10 = 0.f, E11 = 0.f;
        if (tg < 2) {
            int tt = t < TMAXX ? t : TMAXX - 1;
            int xA = __ldg(&x[(b0 + bA) * TMAXX + tt]);
            int xB = __ldg(&x[(b0 + bB) * TMAXX + tt]);
            E00 = __ldg(&g_expEt[xA * S + n0]);        // (n0,   bA)
            E01 = __ldg(&g_expEt[xA * S + n0 + 8]);    // (n0+8, bA)
            E10 = __ldg(&g_expEt[xB * S + n0]);        // (n0,   bB)
            E11 = __ldg(&g_expEt[xB * S + n0 + 8]);    // (n0+8, bB)
        }

        // ---- single wait for buf cur; warp0 re-arms immediately ----
        if (t > 1) {
            mbar_wait(barF + cur * 8, cur ? pf1 : pf0);
            if (cur) pf1 ^= 1; else pf0 ^= 1;
            if (wid == 0 && lane == 0)
                mbar_arrive_expect(barF + cur * 8, 3 * SLICEB);
        }

        // ---- MMA: full K=512, 4 accumulator chains ----
        float a0c = 0.f, a1c = 0.f, a2c = 0.f, a3c = 0.f;
        {
            const uint32_t vwb = smb + B_OFF + cur * BUF_B + g * BROWB + tg * 4;
            float x0 = 0.f, x1 = 0.f, x2 = 0.f, x3 = 0.f;
            float y0 = 0.f, y1 = 0.f, y2 = 0.f, y3 = 0.f;
            float z0 = 0.f, z1 = 0.f, z2 = 0.f, z3 = 0.f;
            #pragma unroll
            for (int c = 0; c < 32; c += 4) {
                uint32_t o0 = (uint32_t)(((c + 0) >> 3) * SLICEB + ((c + 0) & 7) * 32);
                uint32_t o1 = (uint32_t)(((c + 1) >> 3) * SLICEB + ((c + 1) & 7) * 32);
                uint32_t o2 = (uint32_t)(((c + 2) >> 3) * SLICEB + ((c + 2) & 7) * 32);
                uint32_t o3 = (uint32_t)(((c + 3) >> 3) * SLICEB + ((c + 3) & 7) * 32);
                uint32_t p0 = lds_u32(vwb + o0), p1 = lds_u32(vwb + o0 + 16);
                uint32_t q0 = lds_u32(vwb + o1), q1 = lds_u32(vwb + o1 + 16);
                uint32_t r0 = lds_u32(vwb + o2), r1 = lds_u32(vwb + o2 + 16);
                uint32_t s0 = lds_u32(vwb + o3), s1 = lds_u32(vwb + o3 + 16);
                mma16816(a0c, a1c, a2c, a3c, Ar[c][0], Ar[c][1], Ar[c][2], Ar[c][3], p0, p1);
                mma16816(x0, x1, x2, x3, Ar[c + 1][0], Ar[c + 1][1], Ar[c + 1][2], Ar[c + 1][3], q0, q1);
                mma16816(y0, y1, y2, y3, Ar[c + 2][0], Ar[c + 2][1], Ar[c + 2][2], Ar[c + 2][3], r0, r1);
                mma16816(z0, z1, z2, z3, Ar[c + 3][0], Ar[c + 3][1], Ar[c + 3][2], Ar[c + 3][3], s0, s1);
            }
            a0c += x0 + y0 + z0;
            a1c += x1 + y1 + z1;
            a2c += x2 + y2 + z2;
            a3c += x3 + y3 + z3;
        }

        // ---- z / rz / bookkeeping (issues under HMMA shadow) ----
        float rzv = 0.f;
        {
            float z4 = 0.f;
            if (lane < 16)
                z4 = *(float*)(smc + B_OFF + cur * BUF_B + (lane >> 2) * SLICEB + ZPOFF + (lane & 3) * 4);
            z4 += __shfl_xor_sync(0xffffffffu, z4, 4);
            z4 += __shfl_xor_sync(0xffffffffu, z4, 8);   // lanes 0-15: total z for b=lane&3
            if (wid == 0 && lane < 4) {
                float lz = logf(z4);
                if (rank == 0 && Ts_sh[lane] == t) out[b0 + lane] = (float)(off + (double)lz);
                off += (double)lz;
            }
            if (lane < 4) rzv = __fdividef(1.f, z4);
        }
        if (t == maxT) break;
        float rzA = __shfl_sync(0xffffffffu, rzv, bAc);
        float rzB = __shfl_sync(0xffffffffu, rzv, bBc);

        // ---- epilogue: scale fragments; stores guarded, shuffles NOT ----
        float zsA = 0.f, zsB = 0.f;
        {
            float w00 = a0c * E00 * rzA;   // (n0,   bA)
            float w01 = a1c * E10 * rzB;   // (n0,   bB)
            float w10 = a2c * E01 * rzA;   // (n0+8, bA)
            float w11 = a3c * E11 * rzB;   // (n0+8, bB)
            if (tg < 2) {
                const uint32_t slb = smb + B_OFF + nxt * BUF_B + rank * SLICEB;
                int nl0 = mrow + g;
                *(uint16_t*)(smc + (slb - smb) + bA * BROWB + nl0 * 2)       = __bfloat16_as_ushort(__float2bfloat16(w00));
                *(uint16_t*)(smc + (slb - smb) + bA * BROWB + (nl0 + 8) * 2) = __bfloat16_as_ushort(__float2bfloat16(w10));
                *(uint16_t*)(smc + (slb - smb) + bB * BROWB + nl0 * 2)       = __bfloat16_as_ushort(__float2bfloat16(w01));
                *(uint16_t*)(smc + (slb - smb) + bB * BROWB + (nl0 + 8) * 2) = __bfloat16_as_ushort(__float2bfloat16(w11));
                zsA = w00 + w10;
                zsB = w01 + w11;
            }
            // full-mask butterflies executed by ALL lanes (tg>=2 contribute 0)
            #pragma unroll
            for (int o = 4; o <= 16; o <<= 1) {
                zsA += __shfl_xor_sync(0xffffffffu, zsA, o);
                zsB += __shfl_xor_sync(0xffffffffu, zsB, o);
            }
            if (g == 0 && tg < 2) {
                ZRf[wid * 4 + bA] = zsA;
                ZRf[wid * 4 + bB] = zsB;
            }
        }

        // ---- main barrier: only warp0 blocks; others run ahead ----
        if (wid != 0) {
            asm volatile("bar.arrive 1, %0;" :: "r"(NT) : "memory");
        } else {
            asm volatile("bar.sync 1, %0;" :: "r"(NT) : "memory");
            const uint32_t slb = smb + B_OFF + nxt * BUF_B + rank * SLICEB;
            // zp totals over 8 warps (ZRf[8][4])
            float zr = ZRf[lane];
            zr += __shfl_xor_sync(0xffffffffu, zr, 4);
            zr += __shfl_xor_sync(0xffffffffu, zr, 8);
            zr += __shfl_xor_sync(0xffffffffu, zr, 16);
            if (lane < 4) *(float*)(smc + (slb - smb) + ZPOFF + lane * 4) = zr;
            __syncwarp();
            if (lane == 0) {
                fence_proxy_async_();
                #pragma unroll
                for (int r = 0; r < CL; r++) {
                    if (r == rank) continue;
                    bulk_s2s(mapa_u32(slb, r), slb, SLICEB,
                             mapa_u32(barF + nxt * 8, r));
                }
                mbar_arrive_local(barF + nxt * 8);   // arrival 2: local slice + zp ready
            }
        }
        cur = nxt;
    }

    cluster_sync_();   // drain in-flight copies before exit
}

// ---------------- launch ----------------
extern "C" void kernel_launch(void* const* d_in, const int* in_sizes, int n_in,
                              void* d_out, int out_size) {
    const int*   x     = (const int*)d_in[0];
    const int*   T     = (const int*)d_in[1];
    const float* pi    = (const float*)d_in[2];
    const float* trans = (const float*)d_in[3];
    const float* emis  = (const float*)d_in[4];
    float* out = (float*)d_out;

    cudaFuncSetAttribute(hmm_main, cudaFuncAttributeMaxDynamicSharedMemorySize, SMEM_BYTES);

    prep_pi<<<1, S>>>(pi);
    prep_A<<<S, 128>>>(trans);
    prep_E<<<S, 256>>>(emis);
    hmm_main<<<NCTAS, NT, SMEM_BYTES>>>(x, T, out);
}